// round 1
// baseline (speedup 1.0000x reference)
#include <cuda_runtime.h>

#define PP    35
#define CIN   7
#define C1    16
#define A1C   32
#define C2    64
#define A2C   128
#define C3    128
#define DD    10
#define HH    200
#define WWG   176
#define VMAX  20000
#define NBUCK 64
#define NCH   (C1 + C2 + C3)   // 208

// ---------------- scratch (static device globals; no allocation) ----------------
__device__ float  g_a1[(size_t)VMAX * PP * A1C];   // 89.6 MB
__device__ float  g_h3[(size_t)VMAX * PP * C3];    // 358.4 MB
__device__ float  g_keep[(size_t)VMAX * PP];
__device__ double g_sumB [NBUCK][NCH];
__device__ double g_sqB  [NBUCK][NCH];
__device__ float  g_scale[NCH];
__device__ float  g_shift[NCH];

// ---------------- zero the stat buckets (every call; graph-replay safe) ---------
__global__ void k_zero_stats() {
    int n = NBUCK * NCH;
    for (int i = blockIdx.x * blockDim.x + threadIdx.x; i < n; i += gridDim.x * blockDim.x) {
        ((double*)g_sumB)[i] = 0.0;
        ((double*)g_sqB)[i]  = 0.0;
    }
}

// ---------------- pass 1: stats of h1 = x@W1 + b1 (16 ch) -----------------------
__global__ void k_stats1(const float* __restrict__ x,
                         const float* __restrict__ W1,
                         const float* __restrict__ b1, int V) {
    int N = V * PP;
    float lsum[C1], lsq[C1];
    #pragma unroll
    for (int u = 0; u < C1; u++) { lsum[u] = 0.f; lsq[u] = 0.f; }

    for (int r = blockIdx.x * blockDim.x + threadIdx.x; r < N; r += gridDim.x * blockDim.x) {
        float xv[CIN];
        #pragma unroll
        for (int c = 0; c < CIN; c++) xv[c] = x[(size_t)r * CIN + c];
        #pragma unroll
        for (int u = 0; u < C1; u++) {
            float h = b1[u];
            #pragma unroll
            for (int c = 0; c < CIN; c++) h = fmaf(xv[c], W1[c * C1 + u], h);
            lsum[u] += h; lsq[u] += h * h;
        }
    }
    __shared__ float ssum[C1], ssq[C1];
    if (threadIdx.x < C1) { ssum[threadIdx.x] = 0.f; ssq[threadIdx.x] = 0.f; }
    __syncthreads();
    #pragma unroll
    for (int u = 0; u < C1; u++) { atomicAdd(&ssum[u], lsum[u]); atomicAdd(&ssq[u], lsq[u]); }
    __syncthreads();
    if (threadIdx.x < C1) {
        int b = blockIdx.x & (NBUCK - 1);
        atomicAdd(&g_sumB[b][threadIdx.x], (double)ssum[threadIdx.x]);
        atomicAdd(&g_sqB [b][threadIdx.x], (double)ssq [threadIdx.x]);
    }
}

// ---------------- finalize BN params for a stage ---------------------------------
__global__ void k_finalize(const float* __restrict__ g, const float* __restrict__ be,
                           int off, int nc, double invN) {
    int u = threadIdx.x;
    if (u < nc) {
        double s = 0.0, q = 0.0;
        for (int b = 0; b < NBUCK; b++) { s += g_sumB[b][off + u]; q += g_sqB[b][off + u]; }
        double m   = s * invN;
        double var = q * invN - m * m;
        float  sc  = g[u] * rsqrtf((float)var + 1e-5f);
        g_scale[off + u] = sc;
        g_shift[off + u] = (float)((double)be[u] - m * (double)sc);
    }
}

// ---------------- pass 2: apply BN1+relu, max, concat, keep; h2 stats ------------
__global__ void k_vfe1(const float* __restrict__ x,
                       const float* __restrict__ W1, const float* __restrict__ b1,
                       const float* __restrict__ W2, const float* __restrict__ b2, int V) {
    int v = blockIdx.x;
    if (v >= V) return;
    int t = threadIdx.x;

    __shared__ float s_x[PP * CIN];
    __shared__ float s_keep[PP];
    __shared__ float s_h1[PP * C1];
    __shared__ float s_max[C1];
    __shared__ float s_a1[PP * A1C];
    __shared__ float s_s2[C2], s_q2[C2];

    const float* xb = x + (size_t)v * PP * CIN;
    for (int i = t; i < PP * CIN; i += blockDim.x) s_x[i] = xb[i];
    if (t < C2) { s_s2[t] = 0.f; s_q2[t] = 0.f; }
    __syncthreads();

    if (t < PP) {
        float s = 0.f;
        #pragma unroll
        for (int c = 0; c < CIN; c++) s += s_x[t * CIN + c];
        float k = (s != 0.0f) ? 1.0f : 0.0f;
        s_keep[t] = k;
        g_keep[(size_t)v * PP + t] = k;
    }
    __syncthreads();

    for (int i = t; i < PP * C1; i += blockDim.x) {
        int p = i >> 4, u = i & 15;
        float h = b1[u];
        #pragma unroll
        for (int c = 0; c < CIN; c++) h = fmaf(s_x[p * CIN + c], W1[c * C1 + u], h);
        h = fmaf(h, g_scale[u], g_shift[u]);
        s_h1[i] = fmaxf(h, 0.0f);
    }
    __syncthreads();

    if (t < C1) {
        float m = s_h1[t];
        #pragma unroll 7
        for (int p = 1; p < PP; p++) m = fmaxf(m, s_h1[p * C1 + t]);
        s_max[t] = m;
    }
    __syncthreads();

    float* a1g = g_a1 + (size_t)v * PP * A1C;
    for (int i = t; i < PP * A1C; i += blockDim.x) {
        int p = i >> 5, u = i & 31;
        float val = (u < C1 ? s_h1[p * C1 + u] : s_max[u - C1]) * s_keep[p];
        s_a1[i] = val;
        a1g[i]  = val;
    }
    __syncthreads();

    // h2 = a1 @ W2 + b2 (pre-BN) -> stage-2 stats only
    for (int i = t; i < PP * C2; i += blockDim.x) {
        int p = i >> 6, o = i & 63;
        float acc = b2[o];
        #pragma unroll
        for (int k = 0; k < A1C; k++) acc = fmaf(s_a1[p * A1C + k], W2[k * C2 + o], acc);
        atomicAdd(&s_s2[o], acc);
        atomicAdd(&s_q2[o], acc * acc);
    }
    __syncthreads();
    if (t < C2) {
        int b = blockIdx.x & (NBUCK - 1);
        atomicAdd(&g_sumB[b][C1 + t], (double)s_s2[t]);
        atomicAdd(&g_sqB [b][C1 + t], (double)s_q2[t]);
    }
}

// ---------------- pass 3: VFE2 apply + dense GEMM + stage-3 stats ---------------
__global__ void __launch_bounds__(256) k_vfe2(const float* __restrict__ W2, const float* __restrict__ b2,
                      const float* __restrict__ Wd, const float* __restrict__ bd, int V) {
    int v = blockIdx.x;
    if (v >= V) return;
    int t = threadIdx.x;

    __shared__ float s_a1[PP * A1C];          // 1120
    __shared__ float s_h2[PP * C2];           // 2240
    __shared__ float s_max[C2];
    __shared__ float s_a2[40 * A2C];          // padded to 40 rows (5120)
    __shared__ float s_keep[PP];
    __shared__ float s_s3[C3], s_q3[C3];

    const float* a1g = g_a1 + (size_t)v * PP * A1C;
    for (int i = t; i < PP * A1C; i += 256) s_a1[i] = a1g[i];
    if (t < PP)  s_keep[t] = g_keep[(size_t)v * PP + t];
    if (t < C3) { s_s3[t] = 0.f; s_q3[t] = 0.f; }
    __syncthreads();

    // h2 (recompute), BN2 + relu
    for (int i = t; i < PP * C2; i += 256) {
        int p = i >> 6, o = i & 63;
        float acc = b2[o];
        #pragma unroll
        for (int k = 0; k < A1C; k++) acc = fmaf(s_a1[p * A1C + k], W2[k * C2 + o], acc);
        acc = fmaf(acc, g_scale[C1 + o], g_shift[C1 + o]);
        s_h2[i] = fmaxf(acc, 0.0f);
    }
    __syncthreads();

    if (t < C2) {
        float m = s_h2[t];
        #pragma unroll 7
        for (int p = 1; p < PP; p++) m = fmaxf(m, s_h2[p * C2 + t]);
        s_max[t] = m;
    }
    __syncthreads();

    for (int i = t; i < 40 * A2C; i += 256) {
        int p = i >> 7, u = i & 127;
        float val = 0.0f;
        if (p < PP) val = (u < C2 ? s_h2[p * C2 + u] : s_max[u - C2]) * s_keep[p];
        s_a2[i] = val;
    }
    __syncthreads();

    // dense GEMM: [35 x 128] @ [128 x 128]; 5p x 4o register tile per thread
    int og = (t & 31) * 4;   // output channel group
    int pi = t >> 5;         // 0..7
    float acc[5][4];
    #pragma unroll
    for (int j = 0; j < 5; j++) {
        #pragma unroll
        for (int q = 0; q < 4; q++) acc[j][q] = bd[og + q];
    }

    const float4* Wd4 = (const float4*)Wd;
    #pragma unroll 4
    for (int k = 0; k < A2C; k++) {
        float4 w = Wd4[k * 32 + (og >> 2)];
        #pragma unroll
        for (int j = 0; j < 5; j++) {
            float a = s_a2[(pi + 8 * j) * A2C + k];
            acc[j][0] = fmaf(a, w.x, acc[j][0]);
            acc[j][1] = fmaf(a, w.y, acc[j][1]);
            acc[j][2] = fmaf(a, w.z, acc[j][2]);
            acc[j][3] = fmaf(a, w.w, acc[j][3]);
        }
    }

    float* h3g = g_h3 + (size_t)v * PP * C3;
    float ls[4] = {0.f, 0.f, 0.f, 0.f}, lq[4] = {0.f, 0.f, 0.f, 0.f};
    #pragma unroll
    for (int j = 0; j < 5; j++) {
        int p = pi + 8 * j;
        if (p < PP) {
            #pragma unroll
            for (int q = 0; q < 4; q++) {
                float a = acc[j][q];
                h3g[p * C3 + og + q] = a;
                ls[q] += a; lq[q] += a * a;
            }
        }
    }
    #pragma unroll
    for (int q = 0; q < 4; q++) {
        atomicAdd(&s_s3[og + q], ls[q]);
        atomicAdd(&s_q3[og + q], lq[q]);
    }
    __syncthreads();
    if (t < C3) {
        int b = blockIdx.x & (NBUCK - 1);
        atomicAdd(&g_sumB[b][C1 + C2 + t], (double)s_s3[t]);
        atomicAdd(&g_sqB [b][C1 + C2 + t], (double)s_q3[t]);
    }
}

// ---------------- pass 4: BN3 + relu + max over P + scatter-add -----------------
__global__ void k_scatter(const int* __restrict__ coord, float* __restrict__ out, int V) {
    int v = blockIdx.x;
    if (v >= V) return;
    int u = threadIdx.x;   // 128 threads = 128 channels
    const float* h3g = g_h3 + (size_t)v * PP * C3;
    float sc = g_scale[C1 + C2 + u];
    float sh = g_shift[C1 + C2 + u];
    float m = 0.0f;
    #pragma unroll 7
    for (int p = 0; p < PP; p++) {
        float val = fmaf(h3g[p * C3 + u], sc, sh);
        m = fmaxf(m, fmaxf(val, 0.0f));
    }
    int cz = coord[v * 3 + 0];
    int cy = coord[v * 3 + 1];
    int cx = coord[v * 3 + 2];
    size_t off = (size_t)u * (DD * HH * WWG) + (size_t)cz * (HH * WWG) + (size_t)cy * WWG + cx;
    atomicAdd(out + off, m);
}

// ---------------- launch ---------------------------------------------------------
extern "C" void kernel_launch(void* const* d_in, const int* in_sizes, int n_in,
                              void* d_out, int out_size) {
    const float* x     = (const float*)d_in[0];
    const int*   coord = (const int*)  d_in[1];
    const float* W1 = (const float*)d_in[2];
    const float* b1 = (const float*)d_in[3];
    const float* g1 = (const float*)d_in[4];
    const float* be1= (const float*)d_in[5];
    const float* W2 = (const float*)d_in[6];
    const float* b2 = (const float*)d_in[7];
    const float* g2 = (const float*)d_in[8];
    const float* be2= (const float*)d_in[9];
    const float* Wd = (const float*)d_in[10];
    const float* bd = (const float*)d_in[11];
    const float* gd = (const float*)d_in[12];
    const float* bed= (const float*)d_in[13];

    int V = in_sizes[1] / 3;
    if (V > VMAX) V = VMAX;
    double invN = 1.0 / ((double)V * PP);

    cudaMemsetAsync(d_out, 0, (size_t)out_size * sizeof(float), 0);
    k_zero_stats<<<32, 256>>>();
    k_stats1<<<592, 256>>>(x, W1, b1, V);
    k_finalize<<<1, 256>>>(g1, be1, 0, C1, invN);
    k_vfe1<<<V, 128>>>(x, W1, b1, W2, b2, V);
    k_finalize<<<1, 256>>>(g2, be2, C1, C2, invN);
    k_vfe2<<<V, 256>>>(W2, b2, Wd, bd, V);
    k_finalize<<<1, 256>>>(gd, bed, C1 + C2, C3, invN);
    k_scatter<<<V, 128>>>(coord, (float*)d_out, V);
}

// round 2
// speedup vs baseline: 1.3429x; 1.3429x over previous
#include <cuda_runtime.h>

#define PP    35
#define CIN   7
#define C1    16
#define A1C   32
#define C2    64
#define A2C   128
#define C3    128
#define DD    10
#define HH    200
#define WWG   176
#define VMAX  20000
#define NBUCK 64
#define NCH   (C1 + C2 + C3)   // 208
#define NPAIR 18

// ---------------- scratch (static device globals; no allocation) ----------------
__device__ float  g_h2[(size_t)VMAX * PP * C2];    // 179.2 MB, pre-BN h2
__device__ float  g_keep[(size_t)VMAX * PP];
__device__ float  g_max3[(size_t)VMAX * C3];       // per-voxel max over P of pre-BN h3
__device__ float  g_min3[(size_t)VMAX * C3];
__device__ double g_sumB [NBUCK][NCH];
__device__ double g_sqB  [NBUCK][NCH];
__device__ float  g_scale[NCH];
__device__ float  g_shift[NCH];

// ---------------- f32x2 packed helpers ------------------------------------------
__device__ __forceinline__ unsigned long long pack2(float lo, float hi) {
    unsigned long long r;
    asm("mov.b64 %0, {%1, %2};" : "=l"(r) : "f"(lo), "f"(hi));
    return r;
}
__device__ __forceinline__ float2 unpack2(unsigned long long v) {
    float2 r;
    asm("mov.b64 {%0, %1}, %2;" : "=f"(r.x), "=f"(r.y) : "l"(v));
    return r;
}
__device__ __forceinline__ void fma2(unsigned long long& d, unsigned long long a,
                                     unsigned long long b) {
    asm("fma.rn.f32x2 %0, %1, %2, %0;" : "+l"(d) : "l"(a), "l"(b));
}

// ---------------- zero the stat buckets ------------------------------------------
__global__ void k_zero_stats() {
    int n = NBUCK * NCH;
    for (int i = blockIdx.x * blockDim.x + threadIdx.x; i < n; i += gridDim.x * blockDim.x) {
        ((double*)g_sumB)[i] = 0.0;
        ((double*)g_sqB)[i]  = 0.0;
    }
}

// ---------------- pass 1: stats of h1 = x@W1 + b1 (16 ch) -----------------------
__global__ void k_stats1(const float* __restrict__ x,
                         const float* __restrict__ W1,
                         const float* __restrict__ b1, int V) {
    int N = V * PP;
    float lsum[C1], lsq[C1];
    #pragma unroll
    for (int u = 0; u < C1; u++) { lsum[u] = 0.f; lsq[u] = 0.f; }

    for (int r = blockIdx.x * blockDim.x + threadIdx.x; r < N; r += gridDim.x * blockDim.x) {
        float xv[CIN];
        #pragma unroll
        for (int c = 0; c < CIN; c++) xv[c] = x[(size_t)r * CIN + c];
        #pragma unroll
        for (int u = 0; u < C1; u++) {
            float h = b1[u];
            #pragma unroll
            for (int c = 0; c < CIN; c++) h = fmaf(xv[c], W1[c * C1 + u], h);
            lsum[u] += h; lsq[u] += h * h;
        }
    }
    __shared__ float ssum[C1], ssq[C1];
    if (threadIdx.x < C1) { ssum[threadIdx.x] = 0.f; ssq[threadIdx.x] = 0.f; }
    __syncthreads();
    #pragma unroll
    for (int u = 0; u < C1; u++) { atomicAdd(&ssum[u], lsum[u]); atomicAdd(&ssq[u], lsq[u]); }
    __syncthreads();
    if (threadIdx.x < C1) {
        int b = blockIdx.x & (NBUCK - 1);
        atomicAdd(&g_sumB[b][threadIdx.x], (double)ssum[threadIdx.x]);
        atomicAdd(&g_sqB [b][threadIdx.x], (double)ssq [threadIdx.x]);
    }
}

// ---------------- finalize BN params for a stage ---------------------------------
__global__ void k_finalize(const float* __restrict__ g, const float* __restrict__ be,
                           int off, int nc, double invN) {
    int u = threadIdx.x;
    if (u < nc) {
        double s = 0.0, q = 0.0;
        for (int b = 0; b < NBUCK; b++) { s += g_sumB[b][off + u]; q += g_sqB[b][off + u]; }
        double m   = s * invN;
        double var = q * invN - m * m;
        float  sc  = g[u] * rsqrtf((float)var + 1e-5f);
        g_scale[off + u] = sc;
        g_shift[off + u] = (float)((double)be[u] - m * (double)sc);
    }
}

// ---------------- pass 2: BN1+relu, max, concat, keep; packed h2 GEMM -> g_h2 ---
__global__ void __launch_bounds__(128) k_vfe1(const float* __restrict__ x,
                       const float* __restrict__ W1, const float* __restrict__ b1,
                       const float* __restrict__ W2, const float* __restrict__ b2, int V) {
    int v = blockIdx.x;
    if (v >= V) return;
    int t = threadIdx.x;

    __shared__ float  s_x[PP * CIN];
    __shared__ float  s_keep[PP + 1];
    __shared__ float  s_h1[PP * C1];
    __shared__ float  s_m1[C1];
    __shared__ float2 s_a1p[A1C * NPAIR];     // [k][slot], slot = pg*9 + n, pr = pg + 2n
    __shared__ float  s_w2[A1C * C2];
    __shared__ float  s_rs[128], s_rq[128];

    const float* xb = x + (size_t)v * (PP * CIN);
    for (int i = t; i < PP * CIN; i += 128) s_x[i] = xb[i];
    for (int i = t; i < A1C * C2; i += 128) s_w2[i] = W2[i];
    __syncthreads();

    if (t < PP) {
        float s = 0.f;
        #pragma unroll
        for (int c = 0; c < CIN; c++) s += s_x[t * CIN + c];
        float k = (s != 0.0f) ? 1.0f : 0.0f;
        s_keep[t] = k;
        g_keep[(size_t)v * PP + t] = k;
    }
    __syncthreads();

    for (int i = t; i < PP * C1; i += 128) {
        int p = i >> 4, u = i & 15;
        float h = b1[u];
        #pragma unroll
        for (int c = 0; c < CIN; c++) h = fmaf(s_x[p * CIN + c], W1[c * C1 + u], h);
        h = fmaf(h, g_scale[u], g_shift[u]);
        s_h1[i] = fmaxf(h, 0.0f);
    }
    __syncthreads();

    if (t < C1) {
        float m = s_h1[t];
        #pragma unroll 7
        for (int p = 1; p < PP; p++) m = fmaxf(m, s_h1[p * C1 + t]);
        s_m1[t] = m;
    }
    __syncthreads();

    // build a1 point-pairs
    for (int i = t; i < A1C * NPAIR; i += 128) {
        int k = i / NPAIR, s = i % NPAIR;
        int pg = s / 9, n = s % 9;
        int pr = pg + 2 * n;
        int p0 = 2 * pr, p1 = p0 + 1;
        float u0 = (k < C1 ? s_h1[p0 * C1 + k] : s_m1[k - C1]) * s_keep[p0];
        float u1 = (p1 < PP) ? ((k < C1 ? s_h1[p1 * C1 + k] : s_m1[k - C1]) * s_keep[p1]) : 0.f;
        s_a1p[k * NPAIR + s] = make_float2(u0, u1);
    }
    __syncthreads();

    // packed h2 = a1 @ W2 + b2 (pre-BN) -> g_h2 + stage-2 stats
    int o = t & 63, pg = t >> 6;
    float bo = b2[o];
    unsigned long long acc[9];
    #pragma unroll
    for (int n = 0; n < 9; n++) acc[n] = pack2(bo, bo);

    #pragma unroll 4
    for (int k = 0; k < A1C; k++) {
        float w = s_w2[k * C2 + o];
        unsigned long long wp = pack2(w, w);
        const float2* row = &s_a1p[k * NPAIR + pg * 9];
        #pragma unroll
        for (int n = 0; n < 9; n++)
            fma2(acc[n], *(const unsigned long long*)&row[n], wp);
    }

    float lsum = 0.f, lsq = 0.f;
    float* h2g = g_h2 + (size_t)v * (PP * C2);
    #pragma unroll
    for (int n = 0; n < 9; n++) {
        int pr = pg + 2 * n, p0 = 2 * pr;
        float2 r = unpack2(acc[n]);
        h2g[p0 * C2 + o] = r.x; lsum += r.x; lsq += r.x * r.x;
        if (p0 + 1 < PP) {
            h2g[(p0 + 1) * C2 + o] = r.y; lsum += r.y; lsq += r.y * r.y;
        }
    }
    s_rs[t] = lsum; s_rq[t] = lsq;
    __syncthreads();
    if (t < C2) {
        int b = v & (NBUCK - 1);
        atomicAdd(&g_sumB[b][C1 + t], (double)(s_rs[t] + s_rs[t + 64]));
        atomicAdd(&g_sqB [b][C1 + t], (double)(s_rq[t] + s_rq[t + 64]));
    }
}

// ---------------- pass 3: BN2 apply + packed dense GEMM + stats + max/min -------
__global__ void __launch_bounds__(96) k_vfe2(const float4* __restrict__ Wd4,
                                             const float4* __restrict__ bd4, int V) {
    int v = blockIdx.x;
    if (v >= V) return;
    int t = threadIdx.x;

    __shared__ float  s_hb[PP * C2];           // post BN2+relu
    __shared__ float  s_m2[C2];
    __shared__ float  s_keep[PP + 1];
    __shared__ float2 s_a2p[A2C * NPAIR];      // [k][slot], slot = pi*6 + j, pr = pi + 3j
    __shared__ float  s_sum[96 * 4], s_sq[96 * 4], s_mx[96 * 4], s_mn[96 * 4];

    const float* h2g = g_h2 + (size_t)v * (PP * C2);
    for (int i = t; i < PP * C2; i += 96) {
        int u = i & 63;
        float h = fmaf(h2g[i], g_scale[C1 + u], g_shift[C1 + u]);
        s_hb[i] = fmaxf(h, 0.0f);
    }
    if (t < PP) s_keep[t] = g_keep[(size_t)v * PP + t];
    __syncthreads();

    if (t < C2) {
        float m = s_hb[t];
        #pragma unroll 7
        for (int p = 1; p < PP; p++) m = fmaxf(m, s_hb[p * C2 + t]);
        s_m2[t] = m;
    }
    __syncthreads();

    for (int i = t; i < A2C * NPAIR; i += 96) {
        int k = i / NPAIR, s = i % NPAIR;
        int pi = s / 6, j = s % 6;
        int pr = pi + 3 * j;
        int p0 = 2 * pr, p1 = p0 + 1;
        float u0 = (k < C2 ? s_hb[p0 * C2 + k] : s_m2[k - C2]) * s_keep[p0];
        float u1 = (p1 < PP) ? ((k < C2 ? s_hb[p1 * C2 + k] : s_m2[k - C2]) * s_keep[p1]) : 0.f;
        s_a2p[k * NPAIR + s] = make_float2(u0, u1);
    }
    __syncthreads();

    // dense GEMM [36 x 128] @ [128 x 128] packed: 4 outputs x 6 pairs per thread
    int og = (t & 31) * 4, pi = t >> 5;
    float4 bq = __ldg(bd4 + (og >> 2));
    unsigned long long acc[6][4];
    #pragma unroll
    for (int j = 0; j < 6; j++) {
        acc[j][0] = pack2(bq.x, bq.x); acc[j][1] = pack2(bq.y, bq.y);
        acc[j][2] = pack2(bq.z, bq.z); acc[j][3] = pack2(bq.w, bq.w);
    }

    #pragma unroll 2
    for (int k = 0; k < A2C; k++) {
        float4 w = __ldg(Wd4 + k * 32 + (og >> 2));
        unsigned long long w0 = pack2(w.x, w.x), w1 = pack2(w.y, w.y);
        unsigned long long w2 = pack2(w.z, w.z), w3 = pack2(w.w, w.w);
        const float2* row = &s_a2p[k * NPAIR + pi * 6];
        #pragma unroll
        for (int j = 0; j < 6; j++) {
            unsigned long long a = *(const unsigned long long*)&row[j];
            fma2(acc[j][0], a, w0);
            fma2(acc[j][1], a, w1);
            fma2(acc[j][2], a, w2);
            fma2(acc[j][3], a, w3);
        }
    }

    // per-thread stats + max/min over its points (exclude padded p=35)
    float ls[4] = {0, 0, 0, 0}, lq[4] = {0, 0, 0, 0}, lmx[4], lmn[4];
    #pragma unroll
    for (int q = 0; q < 4; q++) { lmx[q] = -3.4e38f; lmn[q] = 3.4e38f; }
    #pragma unroll
    for (int j = 0; j < 6; j++) {
        int pr = pi + 3 * j, p0 = 2 * pr;
        bool has1 = (p0 + 1 < PP);
        #pragma unroll
        for (int q = 0; q < 4; q++) {
            float2 r = unpack2(acc[j][q]);
            ls[q] += r.x; lq[q] += r.x * r.x;
            lmx[q] = fmaxf(lmx[q], r.x); lmn[q] = fminf(lmn[q], r.x);
            if (has1) {
                ls[q] += r.y; lq[q] += r.y * r.y;
                lmx[q] = fmaxf(lmx[q], r.y); lmn[q] = fminf(lmn[q], r.y);
            }
        }
    }
    #pragma unroll
    for (int q = 0; q < 4; q++) {
        s_sum[t * 4 + q] = ls[q]; s_sq[t * 4 + q] = lq[q];
        s_mx [t * 4 + q] = lmx[q]; s_mn[t * 4 + q] = lmn[q];
    }
    __syncthreads();

    if (t < 32) {
        #pragma unroll
        for (int q = 0; q < 4; q++) {
            float S = 0.f, Q = 0.f, MX = -3.4e38f, MN = 3.4e38f;
            #pragma unroll
            for (int pp = 0; pp < 3; pp++) {
                int idx = ((pp * 32) + t) * 4 + q;
                S += s_sum[idx]; Q += s_sq[idx];
                MX = fmaxf(MX, s_mx[idx]); MN = fminf(MN, s_mn[idx]);
            }
            int ch = t * 4 + q;
            g_max3[(size_t)v * C3 + ch] = MX;
            g_min3[(size_t)v * C3 + ch] = MN;
            int b = v & (NBUCK - 1);
            atomicAdd(&g_sumB[b][C1 + C2 + ch], (double)S);
            atomicAdd(&g_sqB [b][C1 + C2 + ch], (double)Q);
        }
    }
}

// ---------------- pass 4: BN3 + relu + max over P (via max/min) + scatter-add ---
__global__ void k_scatter(const int* __restrict__ coord, float* __restrict__ out, int V) {
    int v = blockIdx.x;
    if (v >= V) return;
    int u = threadIdx.x;   // 128 channels
    float sc = g_scale[C1 + C2 + u];
    float sh = g_shift[C1 + C2 + u];
    float h  = (sc >= 0.0f) ? g_max3[(size_t)v * C3 + u] : g_min3[(size_t)v * C3 + u];
    float val = fmaxf(fmaf(h, sc, sh), 0.0f);
    int cz = coord[v * 3 + 0];
    int cy = coord[v * 3 + 1];
    int cx = coord[v * 3 + 2];
    size_t off = (size_t)u * (DD * HH * WWG) + (size_t)cz * (HH * WWG) + (size_t)cy * WWG + cx;
    atomicAdd(out + off, val);
}

// ---------------- launch ---------------------------------------------------------
extern "C" void kernel_launch(void* const* d_in, const int* in_sizes, int n_in,
                              void* d_out, int out_size) {
    const float* x     = (const float*)d_in[0];
    const int*   coord = (const int*)  d_in[1];
    const float* W1 = (const float*)d_in[2];
    const float* b1 = (const float*)d_in[3];
    const float* g1 = (const float*)d_in[4];
    const float* be1= (const float*)d_in[5];
    const float* W2 = (const float*)d_in[6];
    const float* b2 = (const float*)d_in[7];
    const float* g2 = (const float*)d_in[8];
    const float* be2= (const float*)d_in[9];
    const float* Wd = (const float*)d_in[10];
    const float* bd = (const float*)d_in[11];
    const float* gd = (const float*)d_in[12];
    const float* bed= (const float*)d_in[13];

    int V = in_sizes[1] / 3;
    if (V > VMAX) V = VMAX;
    double invN = 1.0 / ((double)V * PP);

    cudaMemsetAsync(d_out, 0, (size_t)out_size * sizeof(float), 0);
    k_zero_stats<<<32, 256>>>();
    k_stats1<<<592, 256>>>(x, W1, b1, V);
    k_finalize<<<1, 256>>>(g1, be1, 0, C1, invN);
    k_vfe1<<<V, 128>>>(x, W1, b1, W2, b2, V);
    k_finalize<<<1, 256>>>(g2, be2, C1, C2, invN);
    k_vfe2<<<V, 96>>>((const float4*)Wd, (const float4*)bd, V);
    k_finalize<<<1, 256>>>(gd, bed, C1 + C2, C3, invN);
    k_scatter<<<V, 128>>>(coord, (float*)d_out, V);
}